// round 4
// baseline (speedup 1.0000x reference)
#include <cuda_runtime.h>

// out[b,c,h,w] = (1/256) * sum_{p,o in 0..8} inp[b, p*9+o, h, w] * sec[b, c, h+p-4, w+o-4]
// B=8, C=256, H=W=128.

#define MD 4
#define NTAPS 81
#define HH 128
#define WW 128
#define CC 256

#define TH 8
#define TW 32
#define CB 32                    // channels staged per iteration
#define NCB (CC/CB)              // 8
#define NCH 4                    // channels per thread
#define NT 512

// smem layout (floats)
#define A_PLANE  (TH*TW)         // 256 floats, even-tap weight plane
#define A_FLOATS (45*A_PLANE)    // 11520
#define B_STRIDE 36              // odd-tap plane row stride (144B, 16B aligned)
#define B_PLANE  (TH*B_STRIDE)   // 288
#define B_FLOATS (36*B_PLANE)    // 10368
#define SSTR 44                  // sec row stride
#define SPLANE (16*SSTR)         // 704 floats / channel
#define S_FLOATS (CB*SPLANE)     // 22528
#define A_OFF 0
#define B_OFF A_FLOATS
#define S_OFF (A_FLOATS + B_FLOATS)
#define SMEM_BYTES ((A_FLOATS + B_FLOATS + S_FLOATS) * 4)   // 177664

typedef unsigned long long u64;

__device__ __forceinline__ void ffma2(u64& acc, u64 a, u64 b) {
    asm("fma.rn.f32x2 %0, %1, %2, %0;" : "+l"(acc) : "l"(a), "l"(b));
}
__device__ __forceinline__ void lds_v2u64(u64& x, u64& y, unsigned addr) {
    asm volatile("ld.shared.v2.b64 {%0,%1},[%2];" : "=l"(x), "=l"(y) : "r"(addr));
}
__device__ __forceinline__ void lds_u64(u64& x, unsigned addr) {
    asm volatile("ld.shared.b64 %0,[%1];" : "=l"(x) : "r"(addr));
}
__device__ __forceinline__ float lo32(u64 a) { return __uint_as_float((unsigned)(a & 0xffffffffull)); }
__device__ __forceinline__ float hi32(u64 a) { return __uint_as_float((unsigned)(a >> 32)); }

__global__ void __launch_bounds__(NT, 1)
corr_transpose_kernel(const float* __restrict__ inp,
                      const float* __restrict__ sec,
                      float* __restrict__ out)
{
    extern __shared__ float smem[];
    float* wsmA = smem + A_OFF;   // [45][8][32]  planes (p,e): tap o=2e
    float* wsmB = smem + B_OFF;   // [36][8][36]  planes (p,d): tap o=2d+1, shifted +1 col
    float* ssm  = smem + S_OFF;   // [32 ch][16 rows][44]

    const int tid = threadIdx.x;
    const int tx  = tid & 7;            // pixel col group (4 px each)
    const int ty  = (tid >> 3) & 7;     // pixel row
    const int cs  = tid >> 6;           // channel subgroup 0..7
    const int gx  = blockIdx.x * TW;
    const int gy  = blockIdx.y * TH;
    const int b   = blockIdx.z;

    // ---- stage even-tap weight planes: A[p*5+e] = inp plane (p*9+2e) ----
    for (int idx = tid; idx < 45 * TH * (TW / 4); idx += NT) {
        int col4 = idx & 7;
        int rest = idx >> 3;
        int row  = rest & 7;
        int pe   = rest >> 3;           // 0..44
        int p = pe / 5, e = pe % 5;
        int d_tap = p * 9 + 2 * e;
        float4 v = *(const float4*)(inp + (((size_t)(b * NTAPS + d_tap) * HH + gy + row) * WW + gx + col4 * 4));
        *(float4*)(wsmA + pe * A_PLANE + row * TW + col4 * 4) = v;
    }

    // ---- stage odd-tap weight planes, shifted by +1 column; zero guard cols ----
    // B[pd][row][c+1] = w[c] for c in 0..31; B[pd][row][0] = B[pd][row][33..35] = 0
    for (int idx = tid; idx < 36 * TH; idx += NT) {
        int row = idx & 7;
        int pd  = idx >> 3;             // 0..35
        int p = pd >> 2, d = pd & 3;
        int d_tap = p * 9 + 2 * d + 1;
        const float* g = inp + (((size_t)(b * NTAPS + d_tap) * HH + gy + row) * WW + gx);
        float* dst = wsmB + pd * B_PLANE + row * B_STRIDE;
        dst[0] = 0.0f;
        #pragma unroll
        for (int c4 = 0; c4 < 8; c4++) {
            float4 v = *(const float4*)(g + 4 * c4);
            dst[4 * c4 + 1] = v.x; dst[4 * c4 + 2] = v.y;
            dst[4 * c4 + 3] = v.z; dst[4 * c4 + 4] = v.w;
        }
        dst[33] = 0.0f; dst[34] = 0.0f; dst[35] = 0.0f;
    }

    const unsigned smbase = (unsigned)__cvta_generic_to_shared(smem);
    const unsigned aaddr  = smbase + (unsigned)((A_OFF + ty * TW + 4 * tx) * 4);
    const unsigned baddr  = smbase + (unsigned)((B_OFF + ty * B_STRIDE + 4 * tx) * 4);
    const unsigned saddr0 = smbase + (unsigned)((S_OFF + (cs * NCH) * SPLANE + ty * SSTR + 4 * tx) * 4);

    const float scale = 1.0f / (float)CC;
    const int srow_t = tid & 15;        // staging row 0..15
    const int sch    = tid >> 4;        // staged channel 0..31

    for (int cb = 0; cb < NCB; cb++) {
        __syncthreads();   // previous compute done before restaging

        // ---- stage 32 channels of sec with halo ----
        {
            const float* gsec = sec + ((size_t)(b * CC + cb * CB + sch) * HH) * WW;
            float* plane = ssm + sch * SPLANE;
            int r = gy + srow_t - MD;
            #pragma unroll
            for (int c4 = 0; c4 < 10; c4++) {
                int c = gx - MD + 4 * c4;
                float4 v = make_float4(0.f, 0.f, 0.f, 0.f);
                if ((unsigned)r < HH) {
                    if (c >= 0 && c <= WW - 4) {
                        v = *(const float4*)(gsec + (size_t)r * WW + c);
                    } else {
                        const float* gr = gsec + (size_t)r * WW;
                        if ((unsigned)(c + 0) < WW) v.x = gr[c + 0];
                        if ((unsigned)(c + 1) < WW) v.y = gr[c + 1];
                        if ((unsigned)(c + 2) < WW) v.z = gr[c + 2];
                        if ((unsigned)(c + 3) < WW) v.w = gr[c + 3];
                    }
                }
                *(float4*)(plane + srow_t * SSTR + 4 * c4) = v;
            }
        }
        __syncthreads();

        // ---- compute: 4 channels x 4 px, parity-split accumulators ----
        u64 accE[NCH][2];   // even taps: pairs (px0,px1),(px2,px3)
        u64 accO[NCH][3];   // odd taps:  pairs (px-1,px0),(px1,px2),(px3,px4)
        #pragma unroll
        for (int j = 0; j < NCH; j++) {
            accE[j][0] = accE[j][1] = 0ull;
            accO[j][0] = accO[j][1] = accO[j][2] = 0ull;
        }

        #pragma unroll 1
        for (int p = 0; p < 9; p++) {
            u64 wE[5][2];
            #pragma unroll
            for (int e = 0; e < 5; e++)
                lds_v2u64(wE[e][0], wE[e][1], aaddr + (unsigned)(((p * 5 + e) * A_PLANE) * 4));
            u64 wO[4][3];
            #pragma unroll
            for (int d = 0; d < 4; d++) {
                unsigned a = baddr + (unsigned)(((p * 4 + d) * B_PLANE) * 4);
                lds_v2u64(wO[d][0], wO[d][1], a);
                lds_u64(wO[d][2], a + 16u);
            }

            #pragma unroll
            for (int j = 0; j < NCH; j++) {
                unsigned sa = saddr0 + (unsigned)((j * SPLANE + p * SSTR) * 4);
                u64 W[6];
                lds_v2u64(W[0], W[1], sa);
                lds_v2u64(W[2], W[3], sa + 16u);
                lds_v2u64(W[4], W[5], sa + 32u);
                #pragma unroll
                for (int e = 0; e < 5; e++) {
                    ffma2(accE[j][0], wE[e][0], W[e]);
                    ffma2(accE[j][1], wE[e][1], W[e + 1]);
                }
                #pragma unroll
                for (int d = 0; d < 4; d++) {
                    ffma2(accO[j][0], wO[d][0], W[d]);
                    ffma2(accO[j][1], wO[d][1], W[d + 1]);
                    ffma2(accO[j][2], wO[d][2], W[d + 2]);
                }
            }
        }

        // ---- combine parities and store 4 channels x 4 px ----
        #pragma unroll
        for (int j = 0; j < NCH; j++) {
            int c = cb * CB + cs * NCH + j;
            float4 o4;
            o4.x = (lo32(accE[j][0]) + hi32(accO[j][0])) * scale;
            o4.y = (hi32(accE[j][0]) + lo32(accO[j][1])) * scale;
            o4.z = (lo32(accE[j][1]) + hi32(accO[j][1])) * scale;
            o4.w = (hi32(accE[j][1]) + lo32(accO[j][2])) * scale;
            *(float4*)(out + (((size_t)(b * CC + c) * HH + gy + ty) * WW + gx + 4 * tx)) = o4;
        }
    }
}

extern "C" void kernel_launch(void* const* d_in, const int* in_sizes, int n_in,
                              void* d_out, int out_size)
{
    const float* inp = (const float*)d_in[0];   // [B, 81, 128, 128]
    const float* sec = (const float*)d_in[1];   // [B, 256, 128, 128]
    float* out = (float*)d_out;                 // [B, 256, 128, 128]

    const int B = in_sizes[0] / (NTAPS * HH * WW);

    cudaFuncSetAttribute(corr_transpose_kernel,
                         cudaFuncAttributeMaxDynamicSharedMemorySize, SMEM_BYTES);

    dim3 grid(WW / TW, HH / TH, B);   // (4, 16, 8)
    corr_transpose_kernel<<<grid, NT, SMEM_BYTES>>>(inp, sec, out);
}